// round 16
// baseline (speedup 1.0000x reference)
#include <cuda_runtime.h>
#include <math.h>

// Problem constants
#define B_    2
#define QS_   2048
#define MS_   2048
#define KS_   4096      // MS + QS
#define H_    1024
#define NH_   16
#define HD_   64
#define SCALE_ 0.125f   // 1/sqrt(64)
#define LOG2E_ 1.4426950408889634f
#define QSCALE_ (SCALE_ * LOG2E_)   // softmax done in exp2 domain
#define LN_EPS_ 1e-5f

// ---------------------------------------------------------------------------
// Scratch (device globals — no runtime allocation allowed)
// ---------------------------------------------------------------------------
__device__ float g_kv  [(size_t)B_ * KS_ * 2 * NH_ * HD_]; // KV projection    [8192,2048]
__device__ float g_q   [(size_t)B_ * QS_ * NH_ * HD_];     // Q projection     [4096,1024]
__device__ float g_att [(size_t)B_ * QS_ * NH_ * HD_];     // attention output [4096,1024]
__device__ float g_proj[(size_t)B_ * QS_ * H_];            // x + att@W_o      [4096,1024]

// ---------------------------------------------------------------------------
// Helpers. mma.tf32 truncates raw fp32 operand bits to tf32 in HW; measured
// rel_err 3.1e-5 — far inside the 1e-3 budget. Enables cp.async byte copies.
// ---------------------------------------------------------------------------
__device__ __forceinline__ uint4 f4_as_u4(float4 v) {
    uint4 r;
    r.x = __float_as_uint(v.x); r.y = __float_as_uint(v.y);
    r.z = __float_as_uint(v.z); r.w = __float_as_uint(v.w);
    return r;
}

// Raw MUFU.EX2 (log2e folded into the Q scale).
__device__ __forceinline__ float fexp2(float x) {
    float r;
    asm("ex2.approx.ftz.f32 %0, %1;" : "=f"(r) : "f"(x));
    return r;
}

__device__ __forceinline__ void mma_tf32(float c[4],
                                         unsigned a0, unsigned a1, unsigned a2, unsigned a3,
                                         unsigned b0, unsigned b1) {
    asm("mma.sync.aligned.m16n8k8.row.col.f32.tf32.tf32.f32 "
        "{%0,%1,%2,%3}, {%4,%5,%6,%7}, {%8,%9}, {%0,%1,%2,%3};"
        : "+f"(c[0]), "+f"(c[1]), "+f"(c[2]), "+f"(c[3])
        : "r"(a0), "r"(a1), "r"(a2), "r"(a3), "r"(b0), "r"(b1));
}

// L2-only staging copy (.cg, 16B): staged tiles are consumed once from smem.
__device__ __forceinline__ void cp_async16(unsigned dst, const void* src) {
    asm volatile("cp.async.cg.shared.global [%0], [%1], 16;" :: "r"(dst), "l"(src));
}
__device__ __forceinline__ void cp_commit() {
    asm volatile("cp.async.commit_group;" ::: "memory");
}
__device__ __forceinline__ void cp_wait0() {
    asm volatile("cp.async.wait_group 0;" ::: "memory");
}
__device__ __forceinline__ void cp_wait1() {
    asm volatile("cp.async.wait_group 1;" ::: "memory");
}

// ---------------------------------------------------------------------------
// tf32 tensor-core GEMM: C[M,N] = A[M,K] @ B[K,N] (+ resid), row-major fp32.
// Block tile 128x128, K-chunk 32. 256 threads = 8 warps (2x4), each warp
// 64x32 via 4x4 fragments of mma.m16n8k8.
// THREE-STAGE cp.async pipeline (round-15 measured tensor=44%/issue=24.6%:
// with 2 stages each copy group had only ONE ~500-cyc compute phase to cover
// DRAM/L2 latency, exposing tail latency at every wait_group 0). Now:
//   iter c: wait_group 1 (oldest group = copy(c) complete; copy(c+1) may
//           still fly)  [last iter: wait_group 0 — no newer groups exist];
//           sync; issue copy(c+2) -> stage (c+2)%3; compute stage c%3.
// Each copy gets TWO compute phases (~1000 cyc) of slack.
// Race: copy into stage c%3 recurs at chunk c+3, issued at iter c+1 AFTER
// its barrier, which post-dates compute(c) on all threads.
// __launch_bounds__(256,2) -> 2 CTAs/SM (measured occ 23%, regs=128).
// CONCAT=1 fuses concat(mem, x); RESID=1 adds resid in the epilogue.
// Smem pads for conflict-free fragment LOADS:
//   As pad 36 (stride%32==4): A-frag bank = 4g + t4  -> bijective over warp
//   Bs pad 136 (stride%32==8): B-frag bank = 8*t4+g  -> bijective over warp
// Stage = 128*36 + 32*136 = 8960 words; 3 stages = 107520 B dynamic smem;
// 2 CTAs x 105 KB = 210 KB <= 228 KB/SM.
// ---------------------------------------------------------------------------
#define GEMM_STAGE_WORDS (128 * 36 + 32 * 136)
#define GEMM_SMEM_BYTES  (3 * GEMM_STAGE_WORDS * 4)

template <int CONCAT, int RESID>
__global__ __launch_bounds__(256, 2) void gemm_tf32(const float* __restrict__ Ax,
                                                    const float* __restrict__ mem,
                                                    const float* __restrict__ Bm,
                                                    const float* __restrict__ resid,
                                                    float* __restrict__ C,
                                                    int M, int N, int K) {
    extern __shared__ __align__(16) unsigned gsm[];

    int tid  = threadIdx.x;
    int lane = tid & 31;
    int wid  = tid >> 5;
    int wm   = wid >> 2;          // 0..1
    int wn   = wid & 3;           // 0..3
    int g    = lane >> 2;         // groupID 0..7
    int t4   = lane & 3;          // 0..3

    int bm = blockIdx.y * 128;
    int bn = blockIdx.x * 128;

    const float* arowp[4];
    unsigned adst[4];
#pragma unroll
    for (int j = 0; j < 4; j++) {
        int idx = tid + 256 * j;       // 128 rows x 8 float4-cols
        int ar  = idx >> 3;
        int ac4 = idx & 7;
        adst[j] = (unsigned)(ar * 36 + ac4 * 4) * 4u;
        if (CONCAT) {
            int grow = bm + ar;
            int b = grow / KS_;
            int s = grow % KS_;
            arowp[j] = (s < MS_)
                ? mem + ((size_t)b * MS_ + s) * H_ + ac4 * 4
                : Ax  + ((size_t)b * QS_ + (s - MS_)) * H_ + ac4 * 4;
        } else {
            arowp[j] = Ax + (size_t)(bm + ar) * K + ac4 * 4;
        }
    }
    const float* browp[4];
    unsigned bdst[4];
#pragma unroll
    for (int j = 0; j < 4; j++) {
        int idx = tid + 256 * j;       // 32 rows x 32 float4-cols
        int br  = idx >> 5;
        int bc4 = idx & 31;
        bdst[j] = (unsigned)(br * 136 + bc4 * 4) * 4u;
        browp[j] = Bm + (size_t)br * N + bn + bc4 * 4;
    }

    unsigned sbase = (unsigned)__cvta_generic_to_shared(gsm);

    float acc[4][4][4];
#pragma unroll
    for (int i = 0; i < 4; i++)
#pragma unroll
        for (int j = 0; j < 4; j++)
#pragma unroll
            for (int v = 0; v < 4; v++) acc[i][j][v] = 0.f;

    int nchunks = K / 32;

    // Prologue: async-copy chunk 0 -> stage 0, chunk 1 -> stage 1
    {
        unsigned aoff = sbase;
        unsigned boff = sbase + 128 * 36 * 4;
#pragma unroll
        for (int j = 0; j < 4; j++) cp_async16(aoff + adst[j], arowp[j]);
#pragma unroll
        for (int j = 0; j < 4; j++) cp_async16(boff + bdst[j], browp[j]);
        cp_commit();
        if (nchunks > 1) {
            aoff = sbase + (unsigned)(GEMM_STAGE_WORDS * 4);
            boff = aoff + 128 * 36 * 4;
#pragma unroll
            for (int j = 0; j < 4; j++) cp_async16(aoff + adst[j], arowp[j] + 32);
#pragma unroll
            for (int j = 0; j < 4; j++) cp_async16(boff + bdst[j], browp[j] + (size_t)32 * N);
            cp_commit();
        }
    }

    int scur = 0;   // stage of chunk c
    int siss = 2;   // stage of chunk c+2
    for (int c = 0; c < nchunks; c++) {
        if (c + 1 < nchunks) cp_wait1();   // oldest group (chunk c) complete
        else                 cp_wait0();   // last chunk: drain everything
        __syncthreads();

        if (c + 2 < nchunks) {
            int k0 = (c + 2) * 32;
            unsigned aoff = sbase + (unsigned)siss * (GEMM_STAGE_WORDS * 4);
            unsigned boff = aoff + 128 * 36 * 4;
#pragma unroll
            for (int j = 0; j < 4; j++) cp_async16(aoff + adst[j], arowp[j] + k0);
#pragma unroll
            for (int j = 0; j < 4; j++) cp_async16(boff + bdst[j], browp[j] + (size_t)k0 * N);
            cp_commit();
        }

        const unsigned* Acur = gsm + scur * GEMM_STAGE_WORDS;
        const unsigned* Bcur = Acur + 128 * 36;
#pragma unroll
        for (int ks = 0; ks < 32; ks += 8) {
            unsigned bf[4][2];
#pragma unroll
            for (int fn = 0; fn < 4; fn++) {
                int cb = wn * 32 + fn * 8 + g;
                bf[fn][0] = Bcur[(ks + t4) * 136 + cb];
                bf[fn][1] = Bcur[(ks + t4 + 4) * 136 + cb];
            }
#pragma unroll
            for (int fm = 0; fm < 4; fm++) {
                int rb = wm * 64 + fm * 16;
                unsigned a0 = Acur[(rb + g) * 36 + ks + t4];
                unsigned a1 = Acur[(rb + g + 8) * 36 + ks + t4];
                unsigned a2 = Acur[(rb + g) * 36 + ks + t4 + 4];
                unsigned a3 = Acur[(rb + g + 8) * 36 + ks + t4 + 4];
#pragma unroll
                for (int fn = 0; fn < 4; fn++)
                    mma_tf32(acc[fm][fn], a0, a1, a2, a3, bf[fn][0], bf[fn][1]);
            }
        }

        scur = (scur == 2) ? 0 : scur + 1;
        siss = (siss == 2) ? 0 : siss + 1;
    }

#pragma unroll
    for (int fm = 0; fm < 4; fm++) {
#pragma unroll
        for (int fn = 0; fn < 4; fn++) {
            int row = bm + wm * 64 + fm * 16 + g;
            int col = bn + wn * 32 + fn * 8 + 2 * t4;
            float2 v0 = make_float2(acc[fm][fn][0], acc[fm][fn][1]);
            float2 v1 = make_float2(acc[fm][fn][2], acc[fm][fn][3]);
            if (RESID) {
                float2 r0 = *(const float2*)&resid[(size_t)row * N + col];
                float2 r1 = *(const float2*)&resid[(size_t)(row + 8) * N + col];
                v0.x += r0.x; v0.y += r0.y;
                v1.x += r1.x; v1.y += r1.y;
            }
            *(float2*)&C[(size_t)row * N + col]       = v0;
            *(float2*)&C[(size_t)(row + 8) * N + col] = v1;
        }
    }
}

// ---------------------------------------------------------------------------
// Tensor-core flash attention with cp.async DOUBLE-BUFFERED K/V tiles.
// (Unchanged from the measured round-15 WIN configuration.)
// One block = (128-query tile, head, batch), 256 threads = 8 warps; warp w
// owns query rows [16w, 16w+16). Q in register A-frags, pre-scaled by
// SCALE*log2(e); online softmax in exp2 domain via raw MUFU.EX2.
// HEAVY-FIRST: qt = 15 - blockIdx.x (work nkt = 2qt+34 spans 34..63).
// Per 64-key tile: wait0; sync; issue cp.async(kt+1) into idle buf; QK mma;
// mask; softmax (frag regs, quad shfl); P->Ps (warp-private); PV mma.
// __launch_bounds__(256,2): 2 CTAs/SM; smem 2 x 104KB = 208KB <= 228KB/SM.
// smem (words): buf0 Ks@0 Vs@4352 | buf1 Ks@8960 Vs@13312 | Ps@17920.
//   Ks/Ps pad 68 (stride%32==4): bank = 4g + t4   bijective over warp
//   Vs    pad 72 (stride%32==8): bank = 8*t4 + g  bijective over warp
// Mask: key k valid iff k <= q + MS; boundary crosses final TWO k-tiles.
// ---------------------------------------------------------------------------
#define ATTN_BUF_WORDS  (64 * 68 + 64 * 72)                 // 8960 per stage
#define ATTN_PS_OFF     (2 * ATTN_BUF_WORDS)                // 17920
#define ATTN_SMEM_BYTES ((ATTN_PS_OFF + 128 * 68) * 4)      // 106496

__global__ __launch_bounds__(256, 2) void attn_kernel() {
    extern __shared__ __align__(16) unsigned smn[];
    unsigned (*Ps)[68] = (unsigned (*)[68])(smn + ATTN_PS_OFF);    // [128][68]

    int qt = (QS_ / 128 - 1) - blockIdx.x;   // heavy-first: qt 15..0
    int h  = blockIdx.y;   // 0..15
    int b  = blockIdx.z;   // 0..1
    int tid  = threadIdx.x;
    int lane = tid & 31;
    int wid  = tid >> 5;        // 0..7
    int g    = lane >> 2;       // 0..7
    int t4   = lane & 3;        // 0..3
    int rb   = wid * 16;        // warp's row base within tile (0..112)

    unsigned sbase = (unsigned)__cvta_generic_to_shared(smn);
    const float* kvbase = &g_kv[((size_t)(b * KS_)) * (2 * NH_ * HD_) + h * HD_];

    int nkt = 2 * qt + 34;   // tiles 0 .. 2qt+33 hold >=1 valid key

    // ---- Prologue: async-copy K/V tile 0 into buf 0 (overlaps Q staging) ----
    {
        unsigned kb = sbase;
        unsigned vb = sbase + 64 * 68 * 4;
#pragma unroll
        for (int it = 0; it < 4; it++) {
            int i = tid + it * 256;        // 64 rows x 16 float4
            int r = i >> 4, c4 = i & 15;
            const float* sp = kvbase + (size_t)r * (2 * NH_ * HD_) + c4 * 4;
            cp_async16(kb + (unsigned)(r * 68 + c4 * 4) * 4u, sp);
            cp_async16(vb + (unsigned)(r * 72 + c4 * 4) * 4u, sp + NH_ * HD_);
        }
        cp_commit();
    }

    // ---- Stage Q (exp2-domain scale) into Ps, lift into register A-frags ----
    {
        float4 qreg[8];
#pragma unroll
        for (int it = 0; it < 8; it++) {
            int i = tid + it * 256;            // 128 rows x 16 float4
            int r = i >> 4, c4 = i & 15;
            qreg[it] = *(const float4*)&g_q[((size_t)(b * QS_ + qt * 128 + r)) * (NH_ * HD_)
                                            + h * HD_ + c4 * 4];
        }
#pragma unroll
        for (int it = 0; it < 8; it++) {
            int i = tid + it * 256;
            int r = i >> 4, c4 = i & 15;
            float4 v = qreg[it];
            v.x *= QSCALE_; v.y *= QSCALE_; v.z *= QSCALE_; v.w *= QSCALE_;
            *(uint4*)&Ps[r][c4 * 4] = f4_as_u4(v);
        }
    }
    __syncthreads();

    unsigned qf[8][4];
#pragma unroll
    for (int ks = 0; ks < 8; ks++) {
        qf[ks][0] = Ps[rb + g][ks * 8 + t4];
        qf[ks][1] = Ps[rb + g + 8][ks * 8 + t4];
        qf[ks][2] = Ps[rb + g][ks * 8 + t4 + 4];
        qf[ks][3] = Ps[rb + g + 8][ks * 8 + t4 + 4];
    }
    // qf reads and later P writes are both confined to this warp's 16-row
    // strip of Ps, so no extra block-level fence is needed before reuse.

    float oacc[8][4];
#pragma unroll
    for (int fn = 0; fn < 8; fn++)
#pragma unroll
        for (int v = 0; v < 4; v++) oacc[fn][v] = 0.f;
    float m_lo = -INFINITY, m_hi = -INFINITY, l_lo = 0.f, l_hi = 0.f;

    for (int kt = 0; kt < nkt; kt++) {
        cp_wait0();
        __syncthreads();

        // Issue next tile's copies into the idle buffer
        if (kt + 1 < nkt) {
            const float* tb = kvbase + (size_t)(kt + 1) * 64 * (2 * NH_ * HD_);
            unsigned kb = sbase + (unsigned)((kt + 1) & 1) * (ATTN_BUF_WORDS * 4);
            unsigned vb = kb + 64 * 68 * 4;
#pragma unroll
            for (int it = 0; it < 4; it++) {
                int i = tid + it * 256;
                int r = i >> 4, c4 = i & 15;
                const float* sp = tb + (size_t)r * (2 * NH_ * HD_) + c4 * 4;
                cp_async16(kb + (unsigned)(r * 68 + c4 * 4) * 4u, sp);
                cp_async16(vb + (unsigned)(r * 72 + c4 * 4) * 4u, sp + NH_ * HD_);
            }
            cp_commit();
        }

        const unsigned (*Ks)[68] = (const unsigned (*)[68])(smn + (kt & 1) * ATTN_BUF_WORDS);
        const unsigned (*Vs)[72] = (const unsigned (*)[72])(smn + (kt & 1) * ATTN_BUF_WORDS + 64 * 68);

        // ---- S' = (Q*log2e*scale) K^T ----
        float sf[8][4];
#pragma unroll
        for (int fn = 0; fn < 8; fn++)
#pragma unroll
            for (int v = 0; v < 4; v++) sf[fn][v] = 0.f;
#pragma unroll
        for (int ks = 0; ks < 8; ks++) {
#pragma unroll
            for (int fn = 0; fn < 8; fn++) {
                unsigned b0 = Ks[fn * 8 + g][ks * 8 + t4];
                unsigned b1 = Ks[fn * 8 + g][ks * 8 + t4 + 4];
                mma_tf32(sf[fn], qf[ks][0], qf[ks][1], qf[ks][2], qf[ks][3], b0, b1);
            }
        }

        // ---- Mask (boundary crosses the final two k-tiles) ----
        if (kt >= nkt - 2) {
#pragma unroll
            for (int fn = 0; fn < 8; fn++) {
#pragma unroll
                for (int e = 0; e < 4; e++) {
                    int row = qt * 128 + rb + g + ((e >> 1) << 3);
                    int col = kt * 64 + fn * 8 + 2 * t4 + (e & 1);
                    if (col > row + MS_) sf[fn][e] = -1e30f;
                }
            }
        }

        // ---- Online softmax in exp2 domain (fragment registers) ----
        float tmax_lo = -INFINITY, tmax_hi = -INFINITY;
#pragma unroll
        for (int fn = 0; fn < 8; fn++) {
            tmax_lo = fmaxf(tmax_lo, fmaxf(sf[fn][0], sf[fn][1]));
            tmax_hi = fmaxf(tmax_hi, fmaxf(sf[fn][2], sf[fn][3]));
        }
        tmax_lo = fmaxf(tmax_lo, __shfl_xor_sync(0xffffffffu, tmax_lo, 1));
        tmax_lo = fmaxf(tmax_lo, __shfl_xor_sync(0xffffffffu, tmax_lo, 2));
        tmax_hi = fmaxf(tmax_hi, __shfl_xor_sync(0xffffffffu, tmax_hi, 1));
        tmax_hi = fmaxf(tmax_hi, __shfl_xor_sync(0xffffffffu, tmax_hi, 2));

        float mn_lo = fmaxf(m_lo, tmax_lo);
        float mn_hi = fmaxf(m_hi, tmax_hi);
        float al_lo = fexp2(m_lo - mn_lo);   // first tile: 2^(-inf) = 0
        float al_hi = fexp2(m_hi - mn_hi);

        float sum_lo = 0.f, sum_hi = 0.f;
#pragma unroll
        for (int fn = 0; fn < 8; fn++) {
            float p0 = fexp2(sf[fn][0] - mn_lo);
            float p1 = fexp2(sf[fn][1] - mn_lo);
            float p2 = fexp2(sf[fn][2] - mn_hi);
            float p3 = fexp2(sf[fn][3] - mn_hi);
            sum_lo += p0 + p1;
            sum_hi += p2 + p3;
            *(uint2*)&Ps[rb + g][fn * 8 + 2 * t4] =
                make_uint2(__float_as_uint(p0), __float_as_uint(p1));
            *(uint2*)&Ps[rb + g + 8][fn * 8 + 2 * t4] =
                make_uint2(__float_as_uint(p2), __float_as_uint(p3));
        }
        sum_lo += __shfl_xor_sync(0xffffffffu, sum_lo, 1);
        sum_lo += __shfl_xor_sync(0xffffffffu, sum_lo, 2);
        sum_hi += __shfl_xor_sync(0xffffffffu, sum_hi, 1);
        sum_hi += __shfl_xor_sync(0xffffffffu, sum_hi, 2);

        l_lo = l_lo * al_lo + sum_lo;
        l_hi = l_hi * al_hi + sum_hi;
        m_lo = mn_lo;
        m_hi = mn_hi;

#pragma unroll
        for (int fn = 0; fn < 8; fn++) {
            oacc[fn][0] *= al_lo;
            oacc[fn][1] *= al_lo;
            oacc[fn][2] *= al_hi;
            oacc[fn][3] *= al_hi;
        }
        __syncwarp();   // P written/read only within this warp's 16-row strip

        // ---- O += P V ----
#pragma unroll
        for (int ks = 0; ks < 8; ks++) {
            unsigned a0 = Ps[rb + g][ks * 8 + t4];
            unsigned a1 = Ps[rb + g + 8][ks * 8 + t4];
            unsigned a2 = Ps[rb + g][ks * 8 + t4 + 4];
            unsigned a3 = Ps[rb + g + 8][ks * 8 + t4 + 4];
#pragma unroll
            for (int fn = 0; fn < 8; fn++) {
                unsigned b0 = Vs[ks * 8 + t4][fn * 8 + g];
                unsigned b1 = Vs[ks * 8 + t4 + 4][fn * 8 + g];
                mma_tf32(oacc[fn], a0, a1, a2, a3, b0, b1);
            }
        }
    }

    // ---- Epilogue: normalize and store ----
    float inv_lo = 1.f / l_lo;
    float inv_hi = 1.f / l_hi;
    int row_lo = b * QS_ + qt * 128 + rb + g;
#pragma unroll
    for (int fn = 0; fn < 8; fn++) {
        int col = h * HD_ + fn * 8 + 2 * t4;
        *(float2*)&g_att[(size_t)row_lo * (NH_ * HD_) + col] =
            make_float2(oacc[fn][0] * inv_lo, oacc[fn][1] * inv_lo);
        *(float2*)&g_att[(size_t)(row_lo + 8) * (NH_ * HD_) + col] =
            make_float2(oacc[fn][2] * inv_hi, oacc[fn][3] * inv_hi);
    }
}

// ---------------------------------------------------------------------------
// LayerNorm over g_proj (residual already fused into the O-proj epilogue):
// out = LN(g_proj) * gamma + beta.  One block per row (H=1024).
// ---------------------------------------------------------------------------
__global__ __launch_bounds__(256) void ln_kernel(const float* __restrict__ gamma,
                                                 const float* __restrict__ beta,
                                                 float* __restrict__ out) {
    int row = blockIdx.x;
    int tid = threadIdx.x;
    size_t base = (size_t)row * H_ + tid * 4;

    float4 pv = *(const float4*)&g_proj[base];
    float y0 = pv.x, y1 = pv.y, y2 = pv.z, y3 = pv.w;

    float sum = y0 + y1 + y2 + y3;
    float sq  = y0 * y0 + y1 * y1 + y2 * y2 + y3 * y3;

    __shared__ float ssum[8], ssq[8];
#pragma unroll
    for (int o = 16; o > 0; o >>= 1) {
        sum += __shfl_xor_sync(0xffffffffu, sum, o);
        sq  += __shfl_xor_sync(0xffffffffu, sq,  o);
    }
    if ((tid & 31) == 0) { ssum[tid >> 5] = sum; ssq[tid >> 5] = sq; }
    __syncthreads();
    float ts = 0.f, tq = 0.f;
#pragma unroll
    for (int i = 0; i < 8; i++) { ts += ssum[i]; tq += ssq[i]; }

    float mu  = ts * (1.f / H_);
    float var = tq * (1.f / H_) - mu * mu;
    float inv = rsqrtf(var + LN_EPS_);

    float4 gv = *(const float4*)&gamma[tid * 4];
    float4 bv = *(const float4*)&beta[tid * 4];
    float4 o;
    o.x = (y0 - mu) * inv * gv.x + bv.x;
    o.y = (y1 - mu) * inv * gv.y + bv.y;
    o.z = (y2 - mu) * inv * gv.z + bv.z;
    o.w = (y3 - mu) * inv * gv.w + bv.w;
    *(float4*)&out[base] = o;
}

// ---------------------------------------------------------------------------
// Launcher (graph-capturable: kernel launches + non-stream attribute/query APIs)
// ---------------------------------------------------------------------------
extern "C" void kernel_launch(void* const* d_in, const int* in_sizes, int n_in,
                              void* d_out, int out_size) {
    (void)in_sizes; (void)n_in; (void)out_size;
    const float* x    = (const float*)d_in[0];
    const float* mem  = (const float*)d_in[1];
    // d_in[2] = mask — analytic (k > q + MS), computed in-kernel, not read.
    const float* W_kv = (const float*)d_in[3];
    const float* W_q  = (const float*)d_in[4];
    const float* W_o  = (const float*)d_in[5];
    const float* ln_g = (const float*)d_in[6];
    const float* ln_b = (const float*)d_in[7];
    float* out = (float*)d_out;

    cudaFuncSetAttribute(attn_kernel, cudaFuncAttributeMaxDynamicSharedMemorySize,
                         ATTN_SMEM_BYTES);
    cudaFuncSetAttribute(gemm_tf32<0, 0>, cudaFuncAttributeMaxDynamicSharedMemorySize,
                         GEMM_SMEM_BYTES);
    cudaFuncSetAttribute(gemm_tf32<1, 0>, cudaFuncAttributeMaxDynamicSharedMemorySize,
                         GEMM_SMEM_BYTES);
    cudaFuncSetAttribute(gemm_tf32<0, 1>, cudaFuncAttributeMaxDynamicSharedMemorySize,
                         GEMM_SMEM_BYTES);

    void *pkv, *pq, *patt, *pproj;
    cudaGetSymbolAddress(&pkv,   g_kv);
    cudaGetSymbolAddress(&pq,    g_q);
    cudaGetSymbolAddress(&patt,  g_att);
    cudaGetSymbolAddress(&pproj, g_proj);

    // 1. KV projection with fused concat: g_kv = concat(mem,x) @ W_kv
    gemm_tf32<1, 0><<<dim3(2048 / 128, (B_ * KS_) / 128), 256, GEMM_SMEM_BYTES>>>(
        x, mem, W_kv, nullptr, (float*)pkv, B_ * KS_, 2 * NH_ * HD_, H_);

    // 2. Q projection: g_q = x @ W_q
    gemm_tf32<0, 0><<<dim3(1024 / 128, (B_ * QS_) / 128), 256, GEMM_SMEM_BYTES>>>(
        x, nullptr, W_q, nullptr, (float*)pq, B_ * QS_, NH_ * HD_, H_);

    // 3. Tensor-core flash attention (128-query tiles, cp.async, heavy-first)
    attn_kernel<<<dim3(QS_ / 128, NH_, B_), 256, ATTN_SMEM_BYTES>>>();

    // 4. Output projection + residual: g_proj = x + g_att @ W_o
    gemm_tf32<0, 1><<<dim3(1024 / 128, (B_ * QS_) / 128), 256, GEMM_SMEM_BYTES>>>(
        (const float*)patt, nullptr, W_o, x, (float*)pproj, B_ * QS_, H_, NH_ * HD_);

    // 5. LayerNorm -> d_out
    ln_kernel<<<B_ * QS_, 256>>>(ln_g, ln_b, out);
}